// round 16
// baseline (speedup 1.0000x reference)
#include <cuda_runtime.h>

// Problem dims
#define B_  64
#define T_  2048
#define E_  256
#define A_  128
#define P_  128
#define R_  1024
#define D_  1024
#define H_  256
#define F_  32
#define KS_ 31
#define PAD_ 15

// ---------------- scratch (no allocations allowed) ----------------
__device__ float g_part[16 * B_ * 4096];      // GEMM partial slabs (gates a/d)
__device__ float g_pq_part[8 * B_ * A_];      // pq partials
__device__ float g_proj_part[8 * B_ * H_];    // proj partials
__device__ float g_ah[B_ * R_];
__device__ float g_ac[B_ * R_];
__device__ float g_energies[B_ * T_];
__device__ float g_ctx[B_ * E_];
__device__ float g_dh[B_ * D_];
__device__ float g_dc[B_ * D_];

// ---------------- helpers ----------------
__device__ __forceinline__ unsigned f2tf(float f) {
    unsigned u;
    asm("cvt.rna.tf32.f32 %0, %1;" : "=r"(u) : "f"(f));
    return u;
}

__device__ __forceinline__ void mma_tf32(float* c,
    unsigned a0, unsigned a1, unsigned a2, unsigned a3,
    unsigned b0, unsigned b1)
{
    asm volatile(
        "mma.sync.aligned.m16n8k8.row.col.f32.tf32.tf32.f32 "
        "{%0,%1,%2,%3}, {%4,%5,%6,%7}, {%8,%9}, {%0,%1,%2,%3};"
        : "+f"(c[0]), "+f"(c[1]), "+f"(c[2]), "+f"(c[3])
        : "r"(a0), "r"(a1), "r"(a2), "r"(a3), "r"(b0), "r"(b1));
}

__device__ __forceinline__ void cp16(void* smem_dst, const void* gsrc) {
    unsigned dst = (unsigned)__cvta_generic_to_shared(smem_dst);
    asm volatile("cp.async.ca.shared.global [%0], [%1], 16;"
                 :: "r"(dst), "l"(gsrc));
}
__device__ __forceinline__ void cp_commit() {
    asm volatile("cp.async.commit_group;");
}
__device__ __forceinline__ void cp_wait1() {
    asm volatile("cp.async.wait_group 1;");
}
__device__ __forceinline__ void cp_wait0() {
    asm volatile("cp.async.wait_group 0;");
}

__device__ __forceinline__ float sigm(float x) { return 1.f / (1.f + __expf(-x)); }
__device__ __forceinline__ float fast_tanh(float x) {
    float e = __expf(2.f * x);
    return 1.f - __fdividef(2.f, e + 1.f);
}

// ---------------- tf32 MMA 3-segment GEMM, split-K, partial-slab output ----------
// Slab y: Cpart[y*64*N + m*N + n]; every (x,y) block writes its slab (zeros ok).
__global__ __launch_bounds__(128) void mma_gemm3(
    const float* __restrict__ x1, const float* __restrict__ W1, int K1, int ld1,
    const float* __restrict__ x2, const float* __restrict__ W2, int K2, int ld2,
    const float* __restrict__ x3, const float* __restrict__ W3, int K3, int ld3,
    float* __restrict__ Cpart, int N)
{
    __shared__ float As[3][64][36];
    __shared__ float Ws[3][32][36];

    const int tid  = threadIdx.x;
    const int lane = tid & 31;
    const int w    = tid >> 5;
    const int gid  = lane >> 2;
    const int tig  = lane & 3;
    const int n0   = blockIdx.x * 32;

    const int S      = gridDim.y;
    const int nt_tot = (K1 + K2 + K3) >> 5;
    const int per    = (nt_tot + S - 1) / S;
    const int gt0    = blockIdx.y * per;
    const int gt1    = min(gt0 + per, nt_tot);

    float acc[4][4] = {};

    int base = 0;
#pragma unroll
    for (int s = 0; s < 3; s++) {
        const float* x  = (s == 0) ? x1 : (s == 1) ? x2 : x3;
        const float* W  = (s == 0) ? W1 : (s == 1) ? W2 : W3;
        const int K     = (s == 0) ? K1 : (s == 1) ? K2 : K3;
        const int ld    = (s == 0) ? ld1 : (s == 1) ? ld2 : ld3;
        if (K == 0) continue;
        const int nts = K >> 5;
        const int lo = max(gt0 - base, 0), hi = min(gt1 - base, nts);
        base += nts;
        if (lo >= hi) continue;

        __syncthreads();

        auto issue = [&](int tile, int buf) {
            int k0 = tile * 32;
#pragma unroll
            for (int r = 0; r < 4; r++) {
                int j = tid + r * 128;
                int m = j >> 3, kq = j & 7;
                cp16(&As[buf][m][kq * 4], x + (size_t)m * K + k0 + kq * 4);
            }
#pragma unroll
            for (int r = 0; r < 2; r++) {
                int j = tid + r * 128;
                int n = j >> 3, kq = j & 7;
                cp16(&Ws[buf][n][kq * 4], W + (size_t)(n0 + n) * ld + k0 + kq * 4);
            }
        };

        issue(lo, 0);
        cp_commit();
        if (hi - lo > 1) issue(lo + 1, 1);
        cp_commit();

        for (int it = lo; it < hi; it++) {
            cp_wait1();
            __syncthreads();
            int nx = it + 2;
            if (nx < hi) issue(nx, (nx - lo) % 3);
            cp_commit();

            const int buf = (it - lo) % 3;
#pragma unroll
            for (int kk = 0; kk < 32; kk += 8) {
                unsigned bb0 = f2tf(Ws[buf][w * 8 + gid][kk + tig]);
                unsigned bb1 = f2tf(Ws[buf][w * 8 + gid][kk + tig + 4]);
#pragma unroll
                for (int mt = 0; mt < 4; mt++) {
                    int ra = mt * 16 + gid;
                    unsigned a0 = f2tf(As[buf][ra][kk + tig]);
                    unsigned a1 = f2tf(As[buf][ra + 8][kk + tig]);
                    unsigned a2 = f2tf(As[buf][ra][kk + tig + 4]);
                    unsigned a3 = f2tf(As[buf][ra + 8][kk + tig + 4]);
                    mma_tf32(acc[mt], a0, a1, a2, a3, bb0, bb1);
                }
            }
        }
    }

    float* C = Cpart + (size_t)blockIdx.y * 64 * N;
    int n = n0 + w * 8 + tig * 2;
#pragma unroll
    for (int mt = 0; mt < 4; mt++) {
        int ra = mt * 16 + gid, rb = ra + 8;
        C[(size_t)ra * N + n]     = acc[mt][0];
        C[(size_t)ra * N + n + 1] = acc[mt][1];
        C[(size_t)rb * N + n]     = acc[mt][2];
        C[(size_t)rb * N + n + 1] = acc[mt][3];
    }
}

// ---------------- LSTM pointwise: sums S partial slabs + biases ----------------
__global__ __launch_bounds__(256) void lstm_pointwise(
    const float* __restrict__ parts, int S,
    const float* __restrict__ b_ih, const float* __restrict__ b_hh,
    const float* __restrict__ c_prev,
    float* __restrict__ h_out, float* __restrict__ c_out, int Nc)
{
    int idx4 = blockIdx.x * blockDim.x + threadIdx.x;
    if (idx4 >= (B_ * 1024) / 4) return;
    int q = Nc / 4;
    int b = idx4 / q, j4 = idx4 - b * q;

    const float4* bi = (const float4*)b_ih;
    const float4* bh = (const float4*)b_hh;
    float4 gi4, gf4, gg4, go4;
    {
        float4 x = bi[j4],         y = bh[j4];
        gi4 = make_float4(x.x + y.x, x.y + y.y, x.z + y.z, x.w + y.w);
        x = bi[q + j4];            y = bh[q + j4];
        gf4 = make_float4(x.x + y.x, x.y + y.y, x.z + y.z, x.w + y.w);
        x = bi[2 * q + j4];        y = bh[2 * q + j4];
        gg4 = make_float4(x.x + y.x, x.y + y.y, x.z + y.z, x.w + y.w);
        x = bi[3 * q + j4];        y = bh[3 * q + j4];
        go4 = make_float4(x.x + y.x, x.y + y.y, x.z + y.z, x.w + y.w);
    }
    for (int s = 0; s < S; s++) {
        const float4* p = (const float4*)(parts + (size_t)s * B_ * 4 * Nc
                                          + (size_t)b * 4 * Nc);
        float4 v;
        v = p[j4];         gi4.x += v.x; gi4.y += v.y; gi4.z += v.z; gi4.w += v.w;
        v = p[q + j4];     gf4.x += v.x; gf4.y += v.y; gf4.z += v.z; gf4.w += v.w;
        v = p[2 * q + j4]; gg4.x += v.x; gg4.y += v.y; gg4.z += v.z; gg4.w += v.w;
        v = p[3 * q + j4]; go4.x += v.x; go4.y += v.y; go4.z += v.z; go4.w += v.w;
    }
    float4 cp4 = ((const float4*)c_prev)[idx4];
    float4 h4, c4;
    { float c2 = sigm(gf4.x) * cp4.x + sigm(gi4.x) * fast_tanh(gg4.x);
      h4.x = sigm(go4.x) * fast_tanh(c2); c4.x = c2; }
    { float c2 = sigm(gf4.y) * cp4.y + sigm(gi4.y) * fast_tanh(gg4.y);
      h4.y = sigm(go4.y) * fast_tanh(c2); c4.y = c2; }
    { float c2 = sigm(gf4.z) * cp4.z + sigm(gi4.z) * fast_tanh(gg4.z);
      h4.z = sigm(go4.z) * fast_tanh(c2); c4.z = c2; }
    { float c2 = sigm(gf4.w) * cp4.w + sigm(gi4.w) * fast_tanh(gg4.w);
      h4.w = sigm(go4.w) * fast_tanh(c2); c4.w = c2; }
    ((float4*)h_out)[idx4] = h4;
    ((float4*)c_out)[idx4] = c4;
}

// ---------------- fused conv31 + MMA location-fc + energy (v3, pq slabs) -------
// grid (T/128, B), 256 threads (8 warps). Warp w owns t-rows [w*16, w*16+16).
__global__ __launch_bounds__(256) void energy_kernel(
    const float* __restrict__ att_w, const float* __restrict__ att_w_cum,
    const float* __restrict__ pm,        // [B,T,A]
    const float* __restrict__ pq_part,   // [8][B][A]
    const float* __restrict__ W_loc,     // [F,2,31]
    const float* __restrict__ W_lfc,     // [A,F]
    const float* __restrict__ W_v,       // [A]
    float* __restrict__ energies)        // [B,T]
{
    __shared__ float s_lfc[128 * 36];
    __shared__ float s_cv[128 * 36];
    __shared__ float s_w[F_ * 2 * KS_];
    __shared__ float s_aw[2 * 158];
    __shared__ float s_pq[128];
    __shared__ float s_wv[128];

    const int b   = blockIdx.y;
    const int t0  = blockIdx.x * 128;
    const int tid = threadIdx.x;
    const int lane = tid & 31, w = tid >> 5;
    const int gid = lane >> 2, tig = lane & 3;

    // cp.async prefetch: lfc, wv
#pragma unroll
    for (int r = 0; r < 4; r++) {
        int idx = tid + r * 256;
        int row = idx >> 3, q = idx & 7;
        cp16(s_lfc + row * 36 + q * 4, W_lfc + row * 32 + q * 4);
    }
    if (tid < 32) cp16(s_wv + tid * 4, W_v + tid * 4);
    cp_commit();

    // halo + conv weights + pq slab sum (plain loads)
    for (int i = tid; i < 158; i += 256) {
        int g = t0 - PAD_ + i;
        bool ok = (g >= 0) && (g < T_);
        s_aw[i]       = ok ? att_w[b * T_ + g] : 0.f;
        s_aw[158 + i] = ok ? att_w_cum[b * T_ + g] : 0.f;
    }
    for (int i = tid; i < F_ * 2 * KS_; i += 256) s_w[i] = W_loc[i];
    if (tid < 128) {
        float v = 0.f;
#pragma unroll
        for (int s = 0; s < 8; s++) v += pq_part[s * (B_ * A_) + b * A_ + tid];
        s_pq[tid] = v;
    }
    __syncthreads();

    // phase 1: conv -> s_cv[t][f]; thread = (f = tid&31, tg = w), 16 t's
    {
        int f = tid & 31;
        float acc[16];
#pragma unroll
        for (int i = 0; i < 16; i++) acc[i] = 0.f;
#pragma unroll
        for (int c = 0; c < 2; c++) {
            float av[46];
#pragma unroll
            for (int i = 0; i < 46; i++) av[i] = s_aw[c * 158 + w * 16 + i];
#pragma unroll
            for (int k = 0; k < KS_; k++) {
                float wv = s_w[(f * 2 + c) * KS_ + k];
#pragma unroll
                for (int tt = 0; tt < 16; tt++) acc[tt] += wv * av[k + tt];
            }
        }
#pragma unroll
        for (int tt = 0; tt < 16; tt++) s_cv[(w * 16 + tt) * 36 + f] = acc[tt];
    }
    cp_wait0();
    __syncthreads();

    // phase 2: MMA la[w*16..+15][0..127] = cv @ lfc^T
    float acc[16][4];
#pragma unroll
    for (int nt = 0; nt < 16; nt++)
#pragma unroll
        for (int i = 0; i < 4; i++) acc[nt][i] = 0.f;

#pragma unroll
    for (int kk = 0; kk < 32; kk += 8) {
        int ra = w * 16 + gid;
        unsigned a0 = f2tf(s_cv[ra * 36 + kk + tig]);
        unsigned a1 = f2tf(s_cv[(ra + 8) * 36 + kk + tig]);
        unsigned a2 = f2tf(s_cv[ra * 36 + kk + tig + 4]);
        unsigned a3 = f2tf(s_cv[(ra + 8) * 36 + kk + tig + 4]);
#pragma unroll
        for (int nt = 0; nt < 16; nt++) {
            unsigned bb0 = f2tf(s_lfc[(nt * 8 + gid) * 36 + kk + tig]);
            unsigned bb1 = f2tf(s_lfc[(nt * 8 + gid) * 36 + kk + tig + 4]);
            mma_tf32(acc[nt], a0, a1, a2, a3, bb0, bb1);
        }
    }

    // phase 3: tanh-reduce in fragment layout; pm direct from global
    {
        int tg0 = t0 + w * 16 + gid;
        const float* pm0 = pm + ((size_t)b * T_ + tg0) * A_;
        const float* pm1 = pm0 + 8 * A_;
        float part0 = 0.f, part1 = 0.f;
#pragma unroll
        for (int nt = 0; nt < 16; nt++) {
            int a0 = nt * 8 + tig * 2;
            float pq0 = s_pq[a0], pq1 = s_pq[a0 + 1];
            float wv0 = s_wv[a0], wv1 = s_wv[a0 + 1];
            float2 p0 = *(const float2*)(pm0 + a0);
            float2 p1 = *(const float2*)(pm1 + a0);
            part0 += fast_tanh(pq0 + p0.x + acc[nt][0]) * wv0
                   + fast_tanh(pq1 + p0.y + acc[nt][1]) * wv1;
            part1 += fast_tanh(pq0 + p1.x + acc[nt][2]) * wv0
                   + fast_tanh(pq1 + p1.y + acc[nt][3]) * wv1;
        }
        part0 += __shfl_xor_sync(0xffffffffu, part0, 1);
        part0 += __shfl_xor_sync(0xffffffffu, part0, 2);
        part1 += __shfl_xor_sync(0xffffffffu, part1, 1);
        part1 += __shfl_xor_sync(0xffffffffu, part1, 2);
        if (tig == 0) {
            energies[b * T_ + tg0]     = part0;
            energies[b * T_ + tg0 + 8] = part1;
        }
    }
}

// ---------------- fused masked softmax + context (1024 threads) ----------------
// grid B_. Softmax over T; weights -> d_out + smem; ctx[b,:] plain store.
__global__ __launch_bounds__(1024) void softmax_ctx_kernel(
    const float* __restrict__ energies, const int* __restrict__ mask,
    const float* __restrict__ memory,
    float* __restrict__ weights, float* __restrict__ ctx)
{
    __shared__ float s_wt[T_];
    __shared__ float s_red[16 * 64 * 4];
    __shared__ float red[32];
    __shared__ float s_bcast;

    int b = blockIdx.x, tid = threadIdx.x;
    int lane = tid & 31, wid = tid >> 5;

    float v0, v1;
    {
        float e0 = energies[b * T_ + tid];
        if (mask[b * T_ + tid] != 0) e0 = -1e30f;
        float e1 = energies[b * T_ + tid + 1024];
        if (mask[b * T_ + tid + 1024] != 0) e1 = -1e30f;
        v0 = e0; v1 = e1;
    }
    float mx = fmaxf(v0, v1);
#pragma unroll
    for (int o = 16; o; o >>= 1) mx = fmaxf(mx, __shfl_xor_sync(0xffffffffu, mx, o));
    if (lane == 0) red[wid] = mx;
    __syncthreads();
    if (tid < 32) {
        float m = red[tid];
#pragma unroll
        for (int o = 16; o; o >>= 1) m = fmaxf(m, __shfl_xor_sync(0xffffffffu, m, o));
        if (tid == 0) s_bcast = m;
    }
    __syncthreads();
    mx = s_bcast;
    v0 = __expf(v0 - mx);
    v1 = __expf(v1 - mx);
    float sum = v0 + v1;
#pragma unroll
    for (int o = 16; o; o >>= 1) sum += __shfl_xor_sync(0xffffffffu, sum, o);
    if (lane == 0) red[wid] = sum;
    __syncthreads();
    if (tid < 32) {
        float m = red[tid];
#pragma unroll
        for (int o = 16; o; o >>= 1) m += __shfl_xor_sync(0xffffffffu, m, o);
        if (tid == 0) s_bcast = m;
    }
    __syncthreads();
    float inv = 1.f / s_bcast;
    v0 *= inv; v1 *= inv;
    weights[b * T_ + tid]        = v0;
    weights[b * T_ + tid + 1024] = v1;
    s_wt[tid]        = v0;
    s_wt[tid + 1024] = v1;
    __syncthreads();

    // ctx: thread = (e4 = tid&63, trow = tid>>6 of 16); t stride 16
    {
        int e4 = tid & 63, trow = tid >> 6;
        const float4* mb = (const float4*)(memory + (size_t)b * T_ * E_);
        float4 acc = make_float4(0.f, 0.f, 0.f, 0.f);
#pragma unroll 8
        for (int t = trow; t < T_; t += 16) {
            float wv = s_wt[t];
            float4 m = mb[t * 64 + e4];
            acc.x += wv * m.x; acc.y += wv * m.y;
            acc.z += wv * m.z; acc.w += wv * m.w;
        }
        ((float4*)s_red)[trow * 64 + e4] = acc;
    }
    __syncthreads();
    if (tid < 64) {
        float4 a = make_float4(0.f, 0.f, 0.f, 0.f);
#pragma unroll
        for (int r = 0; r < 16; r++) {
            float4 p = ((float4*)s_red)[r * 64 + tid];
            a.x += p.x; a.y += p.y; a.z += p.z; a.w += p.w;
        }
        ((float4*)ctx)[b * 64 + tid] = a;
    }
}

// ---------------- proj finalize + stop gate ----------------
__global__ __launch_bounds__(256) void proj_fin_gate_kernel(
    const float* __restrict__ proj_part, const float* __restrict__ b_proj,
    const float* __restrict__ dh, const float* __restrict__ ctx,
    const float* __restrict__ W_gate, const float* __restrict__ b_gate,
    float* __restrict__ out_proj, float* __restrict__ out_stop)
{
    __shared__ float red[8];
    int r = blockIdx.x, tid = threadIdx.x;
    int lane = tid & 31, wid = tid >> 5;

    float v = b_proj[tid];
#pragma unroll
    for (int s = 0; s < 8; s++) v += proj_part[s * (B_ * H_) + r * H_ + tid];
    out_proj[r * H_ + tid] = v;

    float acc = 0.f;
    const float* xr = dh + (size_t)r * D_;
#pragma unroll 4
    for (int k = tid; k < D_; k += 256) acc += xr[k] * W_gate[k];
    acc += ctx[r * E_ + tid] * W_gate[D_ + tid];
#pragma unroll
    for (int o = 16; o; o >>= 1) acc += __shfl_xor_sync(0xffffffffu, acc, o);
    if (lane == 0) red[wid] = acc;
    __syncthreads();
    if (tid < 8) {
        float m = red[tid];
#pragma unroll
        for (int o = 4; o; o >>= 1) m += __shfl_xor_sync(0xffu, m, o);
        if (tid == 0) out_stop[r] = m + b_gate[0];
    }
}

// ---------------- launch ----------------
extern "C" void kernel_launch(void* const* d_in, const int* in_sizes, int n_in,
                              void* d_out, int out_size)
{
    const float* last_frame = (const float*)d_in[0];
    const float* att_h      = (const float*)d_in[1];
    const float* att_c      = (const float*)d_in[2];
    const float* att_w      = (const float*)d_in[3];
    const float* att_w_cum  = (const float*)d_in[4];
    const float* att_ctx    = (const float*)d_in[5];
    const float* dec_h      = (const float*)d_in[6];
    const float* dec_c      = (const float*)d_in[7];
    const float* memory     = (const float*)d_in[8];
    const float* pmem       = (const float*)d_in[9];
    const float* W_ih_a     = (const float*)d_in[10];
    const float* W_hh_a     = (const float*)d_in[11];
    const float* b_ih_a     = (const float*)d_in[12];
    const float* b_hh_a     = (const float*)d_in[13];
    const float* W_q        = (const float*)d_in[14];
    const float* W_v        = (const float*)d_in[15];
    const float* W_loc      = (const float*)d_in[16];
    const float* W_lfc      = (const float*)d_in[17];
    const float* W_ih_d     = (const float*)d_in[18];
    const float* W_hh_d     = (const float*)d_in[19];
    const float* b_ih_d     = (const float*)d_in[20];
    const float* b_hh_d     = (const float*)d_in[21];
    const float* W_proj     = (const float*)d_in[22];
    const float* b_proj     = (const float*)d_in[23];
    const float* W_gate     = (const float*)d_in[24];
    const float* b_gate     = (const float*)d_in[25];
    const int*   mask       = (const int*)d_in[26];

    float* out = (float*)d_out;
    float* out_proj = out;                      // [64,256]
    float* out_stop = out + B_ * H_;            // [64,1]
    float* out_w    = out + B_ * H_ + B_;       // [64,2048]

    float *part, *pq_part, *proj_part, *ah, *ac, *energies, *ctx, *dh, *dc;
    cudaGetSymbolAddress((void**)&part,      g_part);
    cudaGetSymbolAddress((void**)&pq_part,   g_pq_part);
    cudaGetSymbolAddress((void**)&proj_part, g_proj_part);
    cudaGetSymbolAddress((void**)&ah,        g_ah);
    cudaGetSymbolAddress((void**)&ac,        g_ac);
    cudaGetSymbolAddress((void**)&energies,  g_energies);
    cudaGetSymbolAddress((void**)&ctx,       g_ctx);
    cudaGetSymbolAddress((void**)&dh,        g_dh);
    cudaGetSymbolAddress((void**)&dc,        g_dc);

    // 1) attention LSTM gates -> slabs (S=8)
    mma_gemm3<<<dim3(128, 8), 128>>>(last_frame, W_ih_a,       P_, P_ + E_,
                                     att_ctx,    W_ih_a + P_,  E_, P_ + E_,
                                     att_h,      W_hh_a,       R_, R_,
                                     part, 4 * R_);
    // 2) attention LSTM cell (sums 8 slabs + biases)
    lstm_pointwise<<<64, 256>>>(part, 8, b_ih_a, b_hh_a, att_c, ah, ac, R_);
    // 3) pq -> slabs (S=8)
    mma_gemm3<<<dim3(A_ / 32, 8), 128>>>(ah, W_q, R_, R_,
                                         nullptr, nullptr, 0, 0,
                                         nullptr, nullptr, 0, 0,
                                         pq_part, A_);
    // 4) fused conv + MMA-la + energies (sums pq slabs)
    energy_kernel<<<dim3(T_ / 128, B_), 256>>>(
        att_w, att_w_cum, pmem, pq_part, W_loc, W_lfc, W_v, energies);
    // 5) fused softmax + ctx
    softmax_ctx_kernel<<<B_, 1024>>>(energies, mask, memory, out_w, ctx);
    // 6) decoder LSTM gates -> slabs (S=16)
    mma_gemm3<<<dim3(128, 16), 128>>>(ah,    W_ih_d,       R_, R_ + E_,
                                      ctx,   W_ih_d + R_,  E_, R_ + E_,
                                      dec_h, W_hh_d,       D_, D_,
                                      part, 4 * D_);
    // 7) decoder LSTM cell (sums 16 slabs + biases)
    lstm_pointwise<<<64, 256>>>(part, 16, b_ih_d, b_hh_d, dec_c, dh, dc, D_);
    // 8) proj -> slabs (S=8)
    mma_gemm3<<<dim3(H_ / 32, 8), 128>>>(dh,  W_proj,       D_, D_ + E_,
                                         ctx, W_proj + D_,  E_, D_ + E_,
                                         nullptr, nullptr, 0, 0,
                                         proj_part, H_);
    // 9) proj finalize + stop gate
    proj_fin_gate_kernel<<<B_, 256>>>(proj_part, b_proj, dh, ctx,
                                      W_gate, b_gate, out_proj, out_stop);
}

// round 17
// speedup vs baseline: 1.1552x; 1.1552x over previous
#include <cuda_runtime.h>

// Problem dims
#define B_  64
#define T_  2048
#define E_  256
#define A_  128
#define P_  128
#define R_  1024
#define D_  1024
#define H_  256
#define F_  32
#define KS_ 31
#define PAD_ 15

// ---------------- scratch (no allocations allowed) ----------------
__device__ float g_gates_a[B_ * 4096];
__device__ float g_gates_d[B_ * 4096];
__device__ float g_ah[B_ * R_];
__device__ float g_ac[B_ * R_];
__device__ float g_pq[B_ * A_];
__device__ float g_energies[B_ * T_];
__device__ float g_ctx[B_ * E_];
__device__ float g_dh[B_ * D_];
__device__ float g_dc[B_ * D_];
__device__ float g_wcomb[128 * 64];   // [a][ck]: lfc @ wloc, k-major (c*32+k, k=31 pad 0)

// ---------------- helpers ----------------
__device__ __forceinline__ unsigned f2tf(float f) {
    unsigned u;
    asm("cvt.rna.tf32.f32 %0, %1;" : "=r"(u) : "f"(f));
    return u;
}

__device__ __forceinline__ void mma_tf32(float* c,
    unsigned a0, unsigned a1, unsigned a2, unsigned a3,
    unsigned b0, unsigned b1)
{
    asm volatile(
        "mma.sync.aligned.m16n8k8.row.col.f32.tf32.tf32.f32 "
        "{%0,%1,%2,%3}, {%4,%5,%6,%7}, {%8,%9}, {%0,%1,%2,%3};"
        : "+f"(c[0]), "+f"(c[1]), "+f"(c[2]), "+f"(c[3])
        : "r"(a0), "r"(a1), "r"(a2), "r"(a3), "r"(b0), "r"(b1));
}

__device__ __forceinline__ void cp16(void* smem_dst, const void* gsrc) {
    unsigned dst = (unsigned)__cvta_generic_to_shared(smem_dst);
    asm volatile("cp.async.ca.shared.global [%0], [%1], 16;"
                 :: "r"(dst), "l"(gsrc));
}
__device__ __forceinline__ void cp_commit() {
    asm volatile("cp.async.commit_group;");
}
__device__ __forceinline__ void cp_wait1() {
    asm volatile("cp.async.wait_group 1;");
}
__device__ __forceinline__ void cp_wait0() {
    asm volatile("cp.async.wait_group 0;");
}

__device__ __forceinline__ float sigm(float x) { return 1.f / (1.f + __expf(-x)); }
__device__ __forceinline__ float fast_tanh(float x) {
    float e = __expf(2.f * x);
    return 1.f - __fdividef(2.f, e + 1.f);
}

// ---------------- output init: biases/zeros + Wcomb precompute ----------------
__global__ void init_kernel(float* ga, const float* bia, const float* bha,
                            float* gd, const float* bid, const float* bhd,
                            float* pq, float* proj, const float* bp, float* ctx,
                            float* wcomb, const float* W_lfc, const float* W_loc)
{
    int idx = blockIdx.x * blockDim.x + threadIdx.x;   // 0 .. 262143
    int n = idx & 4095;
    ga[idx] = bia[n] + bha[n];
    gd[idx] = bid[n] + bhd[n];
    if (idx < B_ * A_) pq[idx] = 0.f;
    if (idx < B_ * H_) proj[idx] = bp[idx & (H_ - 1)];
    if (idx < B_ * E_) ctx[idx] = 0.f;
    if (idx < 128 * 64) {
        int a = idx >> 6, ck = idx & 63;
        int c = ck >> 5, k = ck & 31;
        float v = 0.f;
        if (k < KS_) {
#pragma unroll
            for (int f = 0; f < F_; f++)
                v += W_lfc[a * F_ + f] * W_loc[(f * 2 + c) * KS_ + k];
        }
        wcomb[idx] = v;
    }
}

// ---------------- tf32 MMA 3-segment GEMM, split-K + cp.async pipeline ----------
__global__ __launch_bounds__(128) void mma_gemm3(
    const float* __restrict__ x1, const float* __restrict__ W1, int K1, int ld1,
    const float* __restrict__ x2, const float* __restrict__ W2, int K2, int ld2,
    const float* __restrict__ x3, const float* __restrict__ W3, int K3, int ld3,
    float* __restrict__ C, int N)
{
    __shared__ float As[3][64][36];
    __shared__ float Ws[3][32][36];

    const int tid  = threadIdx.x;
    const int lane = tid & 31;
    const int w    = tid >> 5;
    const int gid  = lane >> 2;
    const int tig  = lane & 3;
    const int n0   = blockIdx.x * 32;

    const int S      = gridDim.y;
    const int nt_tot = (K1 + K2 + K3) >> 5;
    const int per    = (nt_tot + S - 1) / S;
    const int gt0    = blockIdx.y * per;
    const int gt1    = min(gt0 + per, nt_tot);

    float acc[4][4] = {};

    int base = 0;
#pragma unroll
    for (int s = 0; s < 3; s++) {
        const float* x  = (s == 0) ? x1 : (s == 1) ? x2 : x3;
        const float* W  = (s == 0) ? W1 : (s == 1) ? W2 : W3;
        const int K     = (s == 0) ? K1 : (s == 1) ? K2 : K3;
        const int ld    = (s == 0) ? ld1 : (s == 1) ? ld2 : ld3;
        if (K == 0) continue;
        const int nts = K >> 5;
        const int lo = max(gt0 - base, 0), hi = min(gt1 - base, nts);
        base += nts;
        if (lo >= hi) continue;

        __syncthreads();

        auto issue = [&](int tile, int buf) {
            int k0 = tile * 32;
#pragma unroll
            for (int r = 0; r < 4; r++) {
                int j = tid + r * 128;
                int m = j >> 3, kq = j & 7;
                cp16(&As[buf][m][kq * 4], x + (size_t)m * K + k0 + kq * 4);
            }
#pragma unroll
            for (int r = 0; r < 2; r++) {
                int j = tid + r * 128;
                int n = j >> 3, kq = j & 7;
                cp16(&Ws[buf][n][kq * 4], W + (size_t)(n0 + n) * ld + k0 + kq * 4);
            }
        };

        issue(lo, 0);
        cp_commit();
        if (hi - lo > 1) issue(lo + 1, 1);
        cp_commit();

        for (int it = lo; it < hi; it++) {
            cp_wait1();
            __syncthreads();
            int nx = it + 2;
            if (nx < hi) issue(nx, (nx - lo) % 3);
            cp_commit();

            const int buf = (it - lo) % 3;
#pragma unroll
            for (int kk = 0; kk < 32; kk += 8) {
                unsigned bb0 = f2tf(Ws[buf][w * 8 + gid][kk + tig]);
                unsigned bb1 = f2tf(Ws[buf][w * 8 + gid][kk + tig + 4]);
#pragma unroll
                for (int mt = 0; mt < 4; mt++) {
                    int ra = mt * 16 + gid;
                    unsigned a0 = f2tf(As[buf][ra][kk + tig]);
                    unsigned a1 = f2tf(As[buf][ra + 8][kk + tig]);
                    unsigned a2 = f2tf(As[buf][ra][kk + tig + 4]);
                    unsigned a3 = f2tf(As[buf][ra + 8][kk + tig + 4]);
                    mma_tf32(acc[mt], a0, a1, a2, a3, bb0, bb1);
                }
            }
        }
    }

    int n = n0 + w * 8 + tig * 2;
#pragma unroll
    for (int mt = 0; mt < 4; mt++) {
        int ra = mt * 16 + gid, rb = ra + 8;
        atomicAdd(&C[(size_t)ra * N + n],     acc[mt][0]);
        atomicAdd(&C[(size_t)ra * N + n + 1], acc[mt][1]);
        atomicAdd(&C[(size_t)rb * N + n],     acc[mt][2]);
        atomicAdd(&C[(size_t)rb * N + n + 1], acc[mt][3]);
    }
}

// ---------------- LSTM pointwise (float4 vectorized) ----------------
__global__ __launch_bounds__(256) void lstm_pointwise(
    const float* __restrict__ gates, const float* __restrict__ c_prev,
    float* __restrict__ h_out, float* __restrict__ c_out, int Nc)
{
    int idx4 = blockIdx.x * blockDim.x + threadIdx.x;
    if (idx4 >= (B_ * 1024) / 4) return;
    int b = idx4 / (Nc / 4), j4 = idx4 - b * (Nc / 4);
    const float4* g = (const float4*)(gates + (size_t)b * 4 * Nc);
    int q = Nc / 4;
    float4 gi4 = g[j4];
    float4 gf4 = g[q + j4];
    float4 gg4 = g[2 * q + j4];
    float4 go4 = g[3 * q + j4];
    float4 cp4 = ((const float4*)c_prev)[idx4];
    float4 h4, c4;
    { float c2 = sigm(gf4.x) * cp4.x + sigm(gi4.x) * fast_tanh(gg4.x);
      h4.x = sigm(go4.x) * fast_tanh(c2); c4.x = c2; }
    { float c2 = sigm(gf4.y) * cp4.y + sigm(gi4.y) * fast_tanh(gg4.y);
      h4.y = sigm(go4.y) * fast_tanh(c2); c4.y = c2; }
    { float c2 = sigm(gf4.z) * cp4.z + sigm(gi4.z) * fast_tanh(gg4.z);
      h4.z = sigm(go4.z) * fast_tanh(c2); c4.z = c2; }
    { float c2 = sigm(gf4.w) * cp4.w + sigm(gi4.w) * fast_tanh(gg4.w);
      h4.w = sigm(go4.w) * fast_tanh(c2); c4.w = c2; }
    ((float4*)h_out)[idx4] = h4;
    ((float4*)c_out)[idx4] = c4;
}

// ---------------- energy v4: im2col + MMA (conv folded into Wcomb) -----------
// grid (T/64, B), 256 threads (8 warps). Warp w: tg = w>>1 owns t-rows
// [tg*16, +16); ah = w&1 owns a-cols [ah*64, +64) (nt 0..7).
// la[t][a] = sum_ck s_im[t][ck] * Wcomb[a][ck], K=64 tf32 MMA.
// smem float offsets:
//   s_wc   0      [128][68]
//   s_im   8704   [64][68]
//   s_aw   13056  [2][94] (192 reserved)
//   s_pq   13248  [128]
//   s_wv   13376  [128]
//   s_part 13504  [8][16]
#define ENERGY_SMEM_FLOATS 13632
__global__ __launch_bounds__(256) void energy_kernel(
    const float* __restrict__ att_w, const float* __restrict__ att_w_cum,
    const float* __restrict__ pm,        // [B,T,A]
    const float* __restrict__ pq,        // [B,A]
    const float* __restrict__ wcomb,     // [128][64]
    const float* __restrict__ W_v,       // [A]
    float* __restrict__ energies)        // [B,T]
{
    extern __shared__ float sm[];
    float* s_wc   = sm;
    float* s_im   = sm + 8704;
    float* s_aw   = sm + 13056;
    float* s_pq   = sm + 13248;
    float* s_wv   = sm + 13376;
    float* s_part = sm + 13504;

    const int b   = blockIdx.y;
    const int t0  = blockIdx.x * 64;
    const int tid = threadIdx.x;
    const int lane = tid & 31, w = tid >> 5;
    const int gid = lane >> 2, tig = lane & 3;
    const int tg = w >> 1, ah = w & 1;

    // cp.async prefetch: wcomb, pq, wv
#pragma unroll
    for (int r = 0; r < 8; r++) {
        int idx = tid + r * 256;           // 2048 cp16 for 128x64
        int row = idx >> 4, q = idx & 15;
        cp16(s_wc + row * 68 + q * 4, wcomb + row * 64 + q * 4);
    }
    if (tid < 32)      cp16(s_pq + tid * 4, pq + b * A_ + tid * 4);
    else if (tid < 64) cp16(s_wv + (tid - 32) * 4, W_v + (tid - 32) * 4);
    cp_commit();

    // halo (plain loads)
    for (int i = tid; i < 94; i += 256) {
        int g = t0 - PAD_ + i;
        bool ok = (g >= 0) && (g < T_);
        s_aw[i]      = ok ? att_w[b * T_ + g] : 0.f;
        s_aw[94 + i] = ok ? att_w_cum[b * T_ + g] : 0.f;
    }
    __syncthreads();

    // im2col: s_im[t][ck] = s_aw[c][t + k] (k<31), 0 at k=31
#pragma unroll
    for (int r = 0; r < 16; r++) {
        int idx = tid + r * 256;           // 4096 = 64*64
        int t = idx >> 6, ck = idx & 63;
        int c = ck >> 5, k = ck & 31;
        float v = (k < KS_) ? s_aw[c * 94 + t + k] : 0.f;
        s_im[t * 68 + ck] = v;
    }
    cp_wait0();
    __syncthreads();

    // MMA: la[tg*16..+15][ah*64..+63] = im @ wc^T  (8 k-steps, 8 n-tiles)
    float acc[8][4];
#pragma unroll
    for (int nt = 0; nt < 8; nt++)
#pragma unroll
        for (int i = 0; i < 4; i++) acc[nt][i] = 0.f;

#pragma unroll
    for (int kk = 0; kk < 64; kk += 8) {
        int ra = tg * 16 + gid;
        unsigned a0 = f2tf(s_im[ra * 68 + kk + tig]);
        unsigned a1 = f2tf(s_im[(ra + 8) * 68 + kk + tig]);
        unsigned a2 = f2tf(s_im[ra * 68 + kk + tig + 4]);
        unsigned a3 = f2tf(s_im[(ra + 8) * 68 + kk + tig + 4]);
#pragma unroll
        for (int nt = 0; nt < 8; nt++) {
            int n = ah * 64 + nt * 8 + gid;
            unsigned bb0 = f2tf(s_wc[n * 68 + kk + tig]);
            unsigned bb1 = f2tf(s_wc[n * 68 + kk + tig + 4]);
            mma_tf32(acc[nt], a0, a1, a2, a3, bb0, bb1);
        }
    }

    // tanh-reduce in fragment layout; pm direct from global
    {
        int tg0 = t0 + tg * 16 + gid;
        const float* pm0 = pm + ((size_t)b * T_ + tg0) * A_;
        const float* pm1 = pm0 + 8 * A_;
        float part0 = 0.f, part1 = 0.f;
#pragma unroll
        for (int nt = 0; nt < 8; nt++) {
            int a0 = ah * 64 + nt * 8 + tig * 2;
            float pq0 = s_pq[a0], pq1 = s_pq[a0 + 1];
            float wv0 = s_wv[a0], wv1 = s_wv[a0 + 1];
            float2 p0 = *(const float2*)(pm0 + a0);
            float2 p1 = *(const float2*)(pm1 + a0);
            part0 += fast_tanh(pq0 + p0.x + acc[nt][0]) * wv0
                   + fast_tanh(pq1 + p0.y + acc[nt][1]) * wv1;
            part1 += fast_tanh(pq0 + p1.x + acc[nt][2]) * wv0
                   + fast_tanh(pq1 + p1.y + acc[nt][3]) * wv1;
        }
        part0 += __shfl_xor_sync(0xffffffffu, part0, 1);
        part0 += __shfl_xor_sync(0xffffffffu, part0, 2);
        part1 += __shfl_xor_sync(0xffffffffu, part1, 1);
        part1 += __shfl_xor_sync(0xffffffffu, part1, 2);
        if (tig == 0) {
            s_part[w * 16 + gid]     = part0;
            s_part[w * 16 + gid + 8] = part1;
        }
    }
    __syncthreads();
    if (tid < 64) {
        int tg2 = tid >> 4, r = tid & 15;
        energies[b * T_ + t0 + tid] =
            s_part[(2 * tg2) * 16 + r] + s_part[(2 * tg2 + 1) * 16 + r];
    }
}

// ---------------- masked softmax over T (mask int32) ----------------
__global__ __launch_bounds__(256) void softmax_kernel(
    const float* __restrict__ energies, const int* __restrict__ mask,
    float* __restrict__ weights)
{
    int b = blockIdx.x, tid = threadIdx.x;
    __shared__ float red[8];
    __shared__ float s_bcast;
    float v[8];
    float mx = -3.4e38f;
#pragma unroll
    for (int r = 0; r < 8; r++) {
        int t = tid + r * 256;
        float e = energies[b * T_ + t];
        if (mask[b * T_ + t] != 0) e = -1e30f;
        v[r] = e;
        mx = fmaxf(mx, e);
    }
#pragma unroll
    for (int o = 16; o; o >>= 1) mx = fmaxf(mx, __shfl_xor_sync(0xffffffffu, mx, o));
    if ((tid & 31) == 0) red[tid >> 5] = mx;
    __syncthreads();
    if (tid < 8) {
        float m = red[tid];
#pragma unroll
        for (int o = 4; o; o >>= 1) m = fmaxf(m, __shfl_xor_sync(0xffu, m, o));
        if (tid == 0) s_bcast = m;
    }
    __syncthreads();
    mx = s_bcast;
    float sum = 0.f;
#pragma unroll
    for (int r = 0; r < 8; r++) { v[r] = __expf(v[r] - mx); sum += v[r]; }
#pragma unroll
    for (int o = 16; o; o >>= 1) sum += __shfl_xor_sync(0xffffffffu, sum, o);
    if ((tid & 31) == 0) red[tid >> 5] = sum;
    __syncthreads();
    if (tid < 8) {
        float m = red[tid];
#pragma unroll
        for (int o = 4; o; o >>= 1) m += __shfl_xor_sync(0xffu, m, o);
        if (tid == 0) s_bcast = m;
    }
    __syncthreads();
    float inv = 1.f / s_bcast;
#pragma unroll
    for (int r = 0; r < 8; r++) weights[b * T_ + tid + r * 256] = v[r] * inv;
}

// ---------------- context (split-T, atomic; ctx pre-zeroed by init) ----------
__global__ __launch_bounds__(256) void ctx_kernel(
    const float* __restrict__ weights, const float* __restrict__ memory,
    float* __restrict__ ctx)
{
    int b = blockIdx.y;
    int t0 = blockIdx.x * 128;
    int e = threadIdx.x;
    const float* mb = memory + ((size_t)b * T_ + t0) * E_ + e;
    const float* wb = weights + b * T_ + t0;
    float acc = 0.f;
#pragma unroll 4
    for (int t = 0; t < 128; t++) acc += wb[t] * mb[(size_t)t * E_];
    atomicAdd(&ctx[b * E_ + e], acc);
}

// ---------------- stop gate ----------------
__global__ __launch_bounds__(1024) void gate_kernel(
    const float* __restrict__ dh, const float* __restrict__ ctx,
    const float* __restrict__ W_gate, const float* __restrict__ b_gate,
    float* __restrict__ out_stop)
{
    int gtid = blockIdx.x * 1024 + threadIdx.x;
    int r = gtid >> 5, lane = gtid & 31;
    float acc = 0.f;
    const float* xr = dh + (size_t)r * D_;
#pragma unroll 4
    for (int k = lane; k < D_; k += 32) acc += xr[k] * W_gate[k];
    const float* cr = ctx + (size_t)r * E_;
#pragma unroll 4
    for (int k = lane; k < E_; k += 32) acc += cr[k] * W_gate[D_ + k];
#pragma unroll
    for (int o = 16; o; o >>= 1) acc += __shfl_xor_sync(0xffffffffu, acc, o);
    if (lane == 0) out_stop[r] = acc + b_gate[0];
}

// ---------------- launch ----------------
extern "C" void kernel_launch(void* const* d_in, const int* in_sizes, int n_in,
                              void* d_out, int out_size)
{
    const float* last_frame = (const float*)d_in[0];
    const float* att_h      = (const float*)d_in[1];
    const float* att_c      = (const float*)d_in[2];
    const float* att_w      = (const float*)d_in[3];
    const float* att_w_cum  = (const float*)d_in[4];
    const float* att_ctx    = (const float*)d_in[5];
    const float* dec_h      = (const float*)d_in[6];
    const float* dec_c      = (const float*)d_in[7];
    const float* memory     = (const float*)d_in[8];
    const float* pmem       = (const float*)d_in[9];
    const float* W_ih_a     = (const float*)d_in[10];
    const float* W_hh_a     = (const float*)d_in[11];
    const float* b_ih_a     = (const float*)d_in[12];
    const float* b_hh_a     = (const float*)d_in[13];
    const float* W_q        = (const float*)d_in[14];
    const float* W_v        = (const float*)d_in[15];
    const float* W_loc      = (const float*)d_in[16];
    const float* W_lfc      = (const float*)d_in[17];
    const float* W_ih_d     = (const float*)d_in[18];
    const float* W_hh_d     = (const float*)d_in[19];
    const float* b_ih_d     = (const float*)d_in[20];
    const float* b_hh_d     = (const float*)d_in[21];
    const float* W_proj     = (const float*)d_in[22];
    const float* b_proj     = (const float*)d_in[23];
    const float* W_gate     = (const float*)d_in[24];
    const float* b_gate     = (const float*)d_in[25];
    const int*   mask       = (const int*)d_in[26];

    float* out = (float*)d_out;
    float* out_proj = out;                      // [64,256]
    float* out_stop = out + B_ * H_;            // [64,1]
    float* out_w    = out + B_ * H_ + B_;       // [64,2048]

    float *gates_a, *gates_d, *ah, *ac, *pq, *energies, *ctx, *dh, *dc, *wcomb;
    cudaGetSymbolAddress((void**)&gates_a,  g_gates_a);
    cudaGetSymbolAddress((void**)&gates_d,  g_gates_d);
    cudaGetSymbolAddress((void**)&ah,       g_ah);
    cudaGetSymbolAddress((void**)&ac,       g_ac);
    cudaGetSymbolAddress((void**)&pq,       g_pq);
    cudaGetSymbolAddress((void**)&energies, g_energies);
    cudaGetSymbolAddress((void**)&ctx,      g_ctx);
    cudaGetSymbolAddress((void**)&dh,       g_dh);
    cudaGetSymbolAddress((void**)&dc,       g_dc);
    cudaGetSymbolAddress((void**)&wcomb,    g_wcomb);

    const int energy_smem = ENERGY_SMEM_FLOATS * 4;   // 54,528 B
    cudaFuncSetAttribute(energy_kernel,
                         cudaFuncAttributeMaxDynamicSharedMemorySize, energy_smem);

    // 0) init outputs with biases / zeros + Wcomb precompute
    init_kernel<<<1024, 256>>>(gates_a, b_ih_a, b_hh_a,
                               gates_d, b_ih_d, b_hh_d,
                               pq, out_proj, b_proj, ctx,
                               wcomb, W_lfc, W_loc);

    // 1) attention LSTM gates (split-K 8)
    mma_gemm3<<<dim3(128, 8), 128>>>(last_frame, W_ih_a,       P_, P_ + E_,
                                     att_ctx,    W_ih_a + P_,  E_, P_ + E_,
                                     att_h,      W_hh_a,       R_, R_,
                                     gates_a, 4 * R_);
    lstm_pointwise<<<(B_ * R_) / 1024, 256>>>(gates_a, att_c, ah, ac, R_);

    // 2) query projection pq = ah @ W_q^T (split-K 8)
    mma_gemm3<<<dim3(A_ / 32, 8), 128>>>(ah, W_q, R_, R_,
                                         nullptr, nullptr, 0, 0,
                                         nullptr, nullptr, 0, 0,
                                         pq, A_);

    // 3) energy v4 (im2col MMA), then softmax
    energy_kernel<<<dim3(T_ / 64, B_), 256, energy_smem>>>(
        att_w, att_w_cum, pmem, pq, wcomb, W_v, energies);
    softmax_kernel<<<B_, 256>>>(energies, mask, out_w);

    // 4) context
    ctx_kernel<<<dim3(16, B_), 256>>>(out_w, memory, ctx);

    // 5) decoder LSTM gates (split-K 16)
    mma_gemm3<<<dim3(128, 16), 128>>>(ah,    W_ih_d,       R_, R_ + E_,
                                      ctx,   W_ih_d + R_,  E_, R_ + E_,
                                      dec_h, W_hh_d,       D_, D_,
                                      gates_d, 4 * D_);
    lstm_pointwise<<<(B_ * D_) / 1024, 256>>>(gates_d, dec_c, dh, dc, D_);

    // 6) output heads (proj split-K 8)
    mma_gemm3<<<dim3(H_ / 32, 8), 128>>>(dh,  W_proj,       D_, D_ + E_,
                                         ctx, W_proj + D_,  E_, D_ + E_,
                                         nullptr, nullptr, 0, 0,
                                         out_proj, H_);
    gate_kernel<<<2, 1024>>>(dh, ctx, W_gate, b_gate, out_stop);
}